// round 3
// baseline (speedup 1.0000x reference)
#include <cuda_runtime.h>
#include <cuda_bf16.h>

#define BHALF 4096
#define NROW  8192
#define DIM   256
#define INV_T (1.0f/0.07f)
#define LOG2E 1.4426950408889634f

#define TILE_M 128
#define TILE_N 128
#define SM_STRIDE 264            // 256 + 8 bf16 pad -> conflict-free fragment loads
#define TILE_BYTES (TILE_M * SM_STRIDE * 2)          // 67584
#define SMEM_BYTES (3 * TILE_BYTES)                  // A + double-buffered B = 202752

#define NTILE 64                 // 8192 / 128
#define NPAIR 2080               // upper-triangle tile count
#define NBLK  148                // persistent blocks (1 per SM)

__device__ __nv_bfloat16 g_zn[NROW * DIM];   // normalized rows, bf16 (4 MB)
__device__ float g_sumexp[NROW];
__device__ float g_pos[NROW];

// ---------------------------------------------------------------------------
// Kernel A: L2-normalize rows of concat(z_i, z_j) -> bf16; zero accumulators
// ---------------------------------------------------------------------------
__global__ void normalize_kernel(const float* __restrict__ z_i,
                                 const float* __restrict__ z_j) {
    int warp = threadIdx.x >> 5, lane = threadIdx.x & 31;
    int row  = blockIdx.x * 8 + warp;
    const float* src = (row < BHALF) ? (z_i + (size_t)row * DIM)
                                     : (z_j + (size_t)(row - BHALF) * DIM);
    float4 v0 = ((const float4*)src)[lane * 2];
    float4 v1 = ((const float4*)src)[lane * 2 + 1];
    float ss = v0.x*v0.x + v0.y*v0.y + v0.z*v0.z + v0.w*v0.w
             + v1.x*v1.x + v1.y*v1.y + v1.z*v1.z + v1.w*v1.w;
    #pragma unroll
    for (int o = 16; o; o >>= 1) ss += __shfl_xor_sync(0xffffffffu, ss, o);
    float inv = 1.0f / fmaxf(sqrtf(ss), 1e-8f);

    __nv_bfloat162 h0 = __floats2bfloat162_rn(v0.x*inv, v0.y*inv);
    __nv_bfloat162 h1 = __floats2bfloat162_rn(v0.z*inv, v0.w*inv);
    __nv_bfloat162 h2 = __floats2bfloat162_rn(v1.x*inv, v1.y*inv);
    __nv_bfloat162 h3 = __floats2bfloat162_rn(v1.z*inv, v1.w*inv);
    uint4 u;
    u.x = *(unsigned*)&h0; u.y = *(unsigned*)&h1;
    u.z = *(unsigned*)&h2; u.w = *(unsigned*)&h3;
    *(uint4*)(g_zn + (size_t)row * DIM + lane * 8) = u;
    if (lane == 0) { g_sumexp[row] = 0.0f; g_pos[row] = 0.0f; }
}

// ---------------------------------------------------------------------------
// fast exp via 2^y on the FMA pipe (MUFU would bottleneck at 0.5 op/cyc/SM)
// ---------------------------------------------------------------------------
__device__ __forceinline__ float fast_exp2(float y) {
    float t  = y + 12582912.0f;          // round-to-nearest-int trick (1.5*2^23)
    int   i  = __float_as_int(t);
    float nf = t - 12582912.0f;
    float f  = y - nf;                   // f in [-0.5, 0.5]
    float p  = fmaf(1.3333558e-3f, f, 9.6181291e-3f);
    p = fmaf(p, f, 5.5504109e-2f);
    p = fmaf(p, f, 2.4022651e-1f);
    p = fmaf(p, f, 6.9314718e-1f);
    p = fmaf(p, f, 1.0f);
    return p * __int_as_float((i << 23) + 0x3F800000);
}

__device__ __forceinline__ void mma16816(float c[4],
                                         unsigned a0, unsigned a1, unsigned a2, unsigned a3,
                                         unsigned b0, unsigned b1) {
    asm volatile(
        "mma.sync.aligned.m16n8k16.row.col.f32.bf16.bf16.f32 "
        "{%0,%1,%2,%3}, {%4,%5,%6,%7}, {%8,%9}, {%0,%1,%2,%3};\n"
        : "+f"(c[0]), "+f"(c[1]), "+f"(c[2]), "+f"(c[3])
        : "r"(a0), "r"(a1), "r"(a2), "r"(a3), "r"(b0), "r"(b1));
}

__device__ __forceinline__ void cp_async16(void* smem_dst, const void* gsrc) {
    unsigned s = (unsigned)__cvta_generic_to_shared(smem_dst);
    asm volatile("cp.async.cg.shared.global [%0], [%1], 16;\n" :: "r"(s), "l"(gsrc));
}
__device__ __forceinline__ void cp_commit() {
    asm volatile("cp.async.commit_group;\n" ::: "memory");
}
__device__ __forceinline__ void cp_wait1() {
    asm volatile("cp.async.wait_group 1;\n" ::: "memory");
}
__device__ __forceinline__ void cp_wait0() {
    asm volatile("cp.async.wait_group 0;\n" ::: "memory");
}

// decode linear upper-triangle tile index q -> (i, j), row-major over triangle
__device__ __forceinline__ void decode_tile(int q, int& i, int& j) {
    i = 0;
    int rem = q;
    while (rem >= NTILE - i) { rem -= NTILE - i; i++; }
    j = i + rem;
}

// ---------------------------------------------------------------------------
// Kernel B: persistent, balanced symmetric bf16 GEMM over upper-triangle
// tiles, fused exp + diag mask + row AND column sum-of-exp. B double-buffered
// via cp.async; A reloaded only when the row tile changes.
// ---------------------------------------------------------------------------
__global__ void __launch_bounds__(256, 1) ntxent_gemm_kernel() {
    extern __shared__ __nv_bfloat16 smem[];
    __nv_bfloat16* As = smem;
    __nv_bfloat16* Bs0 = smem + TILE_M * SM_STRIDE;
    __nv_bfloat16* Bs[2] = { Bs0, Bs0 + TILE_M * SM_STRIDE };

    int tid  = threadIdx.x;
    int warp = tid >> 5, lane = tid & 31;
    int g    = lane >> 2, tig = lane & 3;
    int wm   = warp >> 2, wn = warp & 3;      // 2x4 warp grid -> 64x32 per warp

    int bid = blockIdx.x;
    int q0  = (int)(((long long)bid * NPAIR) / NBLK);
    int q1  = (int)(((long long)(bid + 1) * NPAIR) / NBLK);

    int i0, j0;
    decode_tile(q0, i0, j0);

    // row-sum accumulators persist across tiles of the same iTile; we flush
    // them whenever iTile changes (and at the end).
    float rsum[4][2];
    #pragma unroll
    for (int mt = 0; mt < 4; mt++) { rsum[mt][0] = 0.f; rsum[mt][1] = 0.f; }

    int iLoaded = -1;
    int iCur = i0, jCur = j0;

    // prologue: start B load for first tile
    {
        const char* gsrc = (const char*)(g_zn + (size_t)jCur * TILE_M * DIM);
        #pragma unroll
        for (int it = 0; it < 16; it++) {
            int idx = tid + it * 256;          // 4096 uint4 total
            int r = idx >> 5, c8 = idx & 31;
            cp_async16(Bs[0] + r * SM_STRIDE + c8 * 8, gsrc + (r * 32 + c8) * 16);
        }
        cp_commit();
    }

    for (int q = q0; q < q1; q++) {
        int buf = (q - q0) & 1;
        int iNext = iCur, jNext = jCur + 1;
        if (jNext == NTILE) { iNext++; jNext = iNext; }

        __syncthreads();   // all warps done computing previous tile; Bs[buf^1] free

        if (q + 1 < q1) {  // prefetch next B tile
            const char* gsrc = (const char*)(g_zn + (size_t)jNext * TILE_M * DIM);
            #pragma unroll
            for (int it = 0; it < 16; it++) {
                int idx = tid + it * 256;
                int r = idx >> 5, c8 = idx & 31;
                cp_async16(Bs[buf ^ 1] + r * SM_STRIDE + c8 * 8,
                           gsrc + (r * 32 + c8) * 16);
            }
        }
        cp_commit();       // always commit (possibly empty group) to keep counts uniform

        if (iCur != iLoaded) {
            // flush row sums of the previous iTile
            if (iLoaded >= 0) {
                #pragma unroll
                for (int mt = 0; mt < 4; mt++)
                    #pragma unroll
                    for (int h = 0; h < 2; h++) {
                        float v = rsum[mt][h];
                        v += __shfl_xor_sync(0xffffffffu, v, 1);
                        v += __shfl_xor_sync(0xffffffffu, v, 2);
                        if (tig == 0)
                            atomicAdd(&g_sumexp[iLoaded * TILE_M + wm * 64 + mt * 16 + g + h * 8], v);
                        rsum[mt][h] = 0.f;
                    }
            }
            const uint4* gsrc = (const uint4*)(g_zn + (size_t)iCur * TILE_M * DIM);
            #pragma unroll
            for (int it = 0; it < 16; it++) {
                int idx = tid + it * 256;
                int r = idx >> 5, c8 = idx & 31;
                *(uint4*)(As + r * SM_STRIDE + c8 * 8) = gsrc[r * 32 + c8];
            }
            iLoaded = iCur;
        }

        cp_wait1();        // current tile's B group complete (next still in flight)
        __syncthreads();

        int rowbase = iCur * TILE_M;
        int colbase = jCur * TILE_M;

        float acc[4][4][4];
        #pragma unroll
        for (int mt = 0; mt < 4; mt++)
            #pragma unroll
            for (int nt = 0; nt < 4; nt++)
                #pragma unroll
                for (int ci = 0; ci < 4; ci++) acc[mt][nt][ci] = 0.f;

        const __nv_bfloat16* Bb = Bs[buf];
        #pragma unroll
        for (int kk = 0; kk < 16; kk++) {
            int k0 = kk * 16 + tig * 2;
            unsigned a[4][4], b[4][2];
            #pragma unroll
            for (int mt = 0; mt < 4; mt++) {
                const __nv_bfloat16* ap = As + (wm * 64 + mt * 16 + g) * SM_STRIDE + k0;
                a[mt][0] = *(const unsigned*)(ap);
                a[mt][1] = *(const unsigned*)(ap + 8 * SM_STRIDE);
                a[mt][2] = *(const unsigned*)(ap + 8);
                a[mt][3] = *(const unsigned*)(ap + 8 * SM_STRIDE + 8);
            }
            #pragma unroll
            for (int nt = 0; nt < 4; nt++) {
                const __nv_bfloat16* bp = Bb + (wn * 32 + nt * 8 + g) * SM_STRIDE + k0;
                b[nt][0] = *(const unsigned*)(bp);
                b[nt][1] = *(const unsigned*)(bp + 8);
            }
            #pragma unroll
            for (int mt = 0; mt < 4; mt++)
                #pragma unroll
                for (int nt = 0; nt < 4; nt++)
                    mma16816(acc[mt][nt], a[mt][0], a[mt][1], a[mt][2], a[mt][3],
                             b[nt][0], b[nt][1]);
        }

        if (jCur == iCur) {
            // Diagonal tile: row sums only, exact diagonal mask.
            #pragma unroll
            for (int mt = 0; mt < 4; mt++) {
                int row0 = rowbase + wm * 64 + mt * 16 + g;
                #pragma unroll
                for (int nt = 0; nt < 4; nt++) {
                    int col0 = colbase + wn * 32 + nt * 8 + tig * 2;
                    #pragma unroll
                    for (int ci = 0; ci < 4; ci++) {
                        int row = row0 + (ci >> 1) * 8;
                        int col = col0 + (ci & 1);
                        float e = fast_exp2(acc[mt][nt][ci] * (INV_T * LOG2E));
                        if (col == row) e = 0.0f;
                        rsum[mt][ci >> 1] += e;
                    }
                }
            }
        } else {
            float csum[4][2];
            #pragma unroll
            for (int nt = 0; nt < 4; nt++) { csum[nt][0] = 0.f; csum[nt][1] = 0.f; }

            bool hasPos = (jCur == iCur + 32);   // contains sim[r, r+4096]
            if (hasPos) {
                #pragma unroll
                for (int mt = 0; mt < 4; mt++) {
                    int row0 = rowbase + wm * 64 + mt * 16 + g;
                    #pragma unroll
                    for (int nt = 0; nt < 4; nt++) {
                        int col0 = colbase + wn * 32 + nt * 8 + tig * 2;
                        #pragma unroll
                        for (int ci = 0; ci < 4; ci++) {
                            int row = row0 + (ci >> 1) * 8;
                            int col = col0 + (ci & 1);
                            float v = acc[mt][nt][ci];
                            float e = fast_exp2(v * (INV_T * LOG2E));
                            if (col == row + BHALF) {
                                g_pos[row] = v * INV_T;
                                g_pos[col] = v * INV_T;
                            }
                            rsum[mt][ci >> 1] += e;
                            csum[nt][ci & 1]  += e;
                        }
                    }
                }
            } else {
                #pragma unroll
                for (int mt = 0; mt < 4; mt++) {
                    #pragma unroll
                    for (int nt = 0; nt < 4; nt++) {
                        #pragma unroll
                        for (int ci = 0; ci < 4; ci++) {
                            float e = fast_exp2(acc[mt][nt][ci] * (INV_T * LOG2E));
                            rsum[mt][ci >> 1] += e;
                            csum[nt][ci & 1]  += e;
                        }
                    }
                }
            }

            // Column reduction: sum over g lanes, then atomic into g_sumexp[col].
            #pragma unroll
            for (int nt = 0; nt < 4; nt++) {
                #pragma unroll
                for (int p = 0; p < 2; p++) {
                    float v = csum[nt][p];
                    v += __shfl_xor_sync(0xffffffffu, v, 4);
                    v += __shfl_xor_sync(0xffffffffu, v, 8);
                    v += __shfl_xor_sync(0xffffffffu, v, 16);
                    if (g == 0) {
                        int col = colbase + wn * 32 + nt * 8 + tig * 2 + p;
                        atomicAdd(&g_sumexp[col], v);
                    }
                }
            }
        }

        iCur = iNext; jCur = jNext;
    }

    // final flush of row sums
    if (iLoaded >= 0) {
        #pragma unroll
        for (int mt = 0; mt < 4; mt++)
            #pragma unroll
            for (int h = 0; h < 2; h++) {
                float v = rsum[mt][h];
                v += __shfl_xor_sync(0xffffffffu, v, 1);
                v += __shfl_xor_sync(0xffffffffu, v, 2);
                if (tig == 0)
                    atomicAdd(&g_sumexp[iLoaded * TILE_M + wm * 64 + mt * 16 + g + h * 8], v);
            }
    }
    cp_wait0();   // drain any dangling (empty) groups before exit
}

// ---------------------------------------------------------------------------
// Kernel C: loss = mean_k( log(sumexp_k) - pos_k )
// ---------------------------------------------------------------------------
__global__ void loss_kernel(float* __restrict__ out) {
    int tid = threadIdx.x;  // 1024
    float s = 0.0f;
    for (int k = tid; k < NROW; k += 1024)
        s += logf(g_sumexp[k]) - g_pos[k];
    #pragma unroll
    for (int o = 16; o; o >>= 1) s += __shfl_xor_sync(0xffffffffu, s, o);
    __shared__ float sw[32];
    if ((tid & 31) == 0) sw[tid >> 5] = s;
    __syncthreads();
    if (tid < 32) {
        float v = sw[tid];
        #pragma unroll
        for (int o = 16; o; o >>= 1) v += __shfl_xor_sync(0xffffffffu, v, o);
        if (tid == 0) out[0] = v / (float)NROW;
    }
}

extern "C" void kernel_launch(void* const* d_in, const int* in_sizes, int n_in,
                              void* d_out, int out_size) {
    const float* z_i = (const float*)d_in[0];
    const float* z_j = (const float*)d_in[1];
    float* out = (float*)d_out;

    cudaFuncSetAttribute(ntxent_gemm_kernel,
                         cudaFuncAttributeMaxDynamicSharedMemorySize, SMEM_BYTES);

    normalize_kernel<<<NROW / 8, 256>>>(z_i, z_j);
    ntxent_gemm_kernel<<<NBLK, 256, SMEM_BYTES>>>();
    loss_kernel<<<1, 1024>>>(out);
}